// round 6
// baseline (speedup 1.0000x reference)
#include <cuda_runtime.h>
#include <math.h>
#include <stdint.h>

#define NN 50000
#define EE 800000
#define HH 128
#define LL 4
#define SB 196   // scan blocks = ceil(NN/256)

// ---------------- scratch (static device globals; no allocation) -------------
__device__ float g_hw[(size_t)NN * HH];       // h @ W result per layer
__device__ float g_h[(size_t)NN * HH];        // activations between layers
__device__ int   g_cnt[NN];
__device__ int   g_cursor[NN];
__device__ int   g_rowstart[NN + 1];
__device__ float g_isd[NN];                   // 1/sqrt(deg)
__device__ float g_invd[NN];                  // 1/deg
__device__ int   g_srcs[EE];                  // CSR: src node per (dst-sorted) edge
__device__ float g_norms[EE];                 // CSR: isd[src]*isd[dst]
__device__ int   g_part[256];                 // scan partials
__device__ float g_whi[(size_t)LL * HH * HH]; // tf32-split W (hi)
__device__ float g_wlo[(size_t)LL * HH * HH]; // tf32-split W (lo)

// ---------------- setup kernels ----------------------------------------------
__global__ void k_init() {
    int i = blockIdx.x * blockDim.x + threadIdx.x;
    if (i < NN) { g_cnt[i] = 0; g_cursor[i] = 0; }
}

__device__ __forceinline__ void tf32_split(float x, float& hi, float& lo) {
    unsigned h, l;
    asm("cvt.rna.tf32.f32 %0, %1;" : "=r"(h) : "f"(x));
    float r = x - __uint_as_float(h);
    asm("cvt.rna.tf32.f32 %0, %1;" : "=r"(l) : "f"(r));
    hi = __uint_as_float(h);
    lo = __uint_as_float(l);
}

__global__ void k_splitw(const float* __restrict__ W) {
    int i = blockIdx.x * blockDim.x + threadIdx.x;   // over LL*HH*HH
    float hi, lo;
    tf32_split(W[i], hi, lo);
    g_whi[i] = hi;
    g_wlo[i] = lo;
}

__global__ void k_count(const int* __restrict__ dst) {
    int e = blockIdx.x * blockDim.x + threadIdx.x;
    if (e < EE) atomicAdd(&g_cnt[dst[e]], 1);
}

__global__ void k_blocksum() {
    int i = blockIdx.x * 256 + threadIdx.x;
    int v = (i < NN) ? g_cnt[i] : 0;
    int lane = threadIdx.x & 31, w = threadIdx.x >> 5;
    __shared__ int ws[8];
#pragma unroll
    for (int o = 16; o > 0; o >>= 1) v += __shfl_down_sync(0xffffffffu, v, o);
    if (lane == 0) ws[w] = v;
    __syncthreads();
    if (threadIdx.x == 0) {
        int s = 0;
#pragma unroll
        for (int j = 0; j < 8; j++) s += ws[j];
        g_part[blockIdx.x] = s;
    }
}

__global__ void k_scanpart() {
    int t = threadIdx.x;
    int v = (t < SB) ? g_part[t] : 0;
    int lane = t & 31, w = t >> 5;
    int x = v;
#pragma unroll
    for (int o = 1; o < 32; o <<= 1) {
        int y = __shfl_up_sync(0xffffffffu, x, o);
        if (lane >= o) x += y;
    }
    __shared__ int ws[8];
    if (lane == 31) ws[w] = x;
    __syncthreads();
    if (t == 0) {
        int run = 0;
#pragma unroll
        for (int j = 0; j < 8; j++) { int tmp = ws[j]; ws[j] = run; run += tmp; }
    }
    __syncthreads();
    int incl = x + ws[w];
    if (t < SB) g_part[t] = incl - v;
}

__global__ void k_blockscan() {
    int b = blockIdx.x;
    int i = b * 256 + threadIdx.x;
    int v = (i < NN) ? g_cnt[i] : 0;
    int lane = threadIdx.x & 31, w = threadIdx.x >> 5;
    int x = v;
#pragma unroll
    for (int o = 1; o < 32; o <<= 1) {
        int y = __shfl_up_sync(0xffffffffu, x, o);
        if (lane >= o) x += y;
    }
    __shared__ int ws[8];
    if (lane == 31) ws[w] = x;
    __syncthreads();
    if (threadIdx.x == 0) {
        int run = 0;
#pragma unroll
        for (int j = 0; j < 8; j++) { int tmp = ws[j]; ws[j] = run; run += tmp; }
    }
    __syncthreads();
    int incl = x + ws[w];
    int ex = incl - v;
    int base = g_part[b];
    if (i < NN) {
        g_rowstart[i] = base + ex;
        float deg = (float)v + 1.0f;
        g_isd[i]  = rsqrtf(deg);
        g_invd[i] = 1.0f / deg;
    }
    if (i == NN - 1) g_rowstart[NN] = base + ex + v;
}

__global__ void k_fill(const int* __restrict__ src, const int* __restrict__ dst) {
    int e = blockIdx.x * blockDim.x + threadIdx.x;
    if (e < EE) {
        int s = src[e], d = dst[e];
        int pos = atomicAdd(&g_cursor[d], 1);
        int idx = g_rowstart[d] + pos;
        g_srcs[idx]  = s;
        g_norms[idx] = g_isd[s] * g_isd[d];
    }
}

// ---------------- 3xTF32 tensor-core GEMM: g_hw = A (Nx128) @ W (128x128) ----
// Tile 128 rows x 128 cols per block (8 warps, 2x4). K chunked 4x32.
// W pre-split in global (g_whi/g_wlo); A split on the fly.
// smem ~71.7KB -> 2 blocks/SM.
#define SA_STRIDE 36
#define SW_STRIDE 136
#define SA_ELEMS (128 * SA_STRIDE)
#define SW_ELEMS (32 * SW_STRIDE)
#define GEMM_SMEM_FLOATS (2 * SA_ELEMS + 2 * SW_ELEMS)

#define MMA8(d, a, b) \
    asm volatile("mma.sync.aligned.m16n8k8.row.col.f32.tf32.tf32.f32 " \
                 "{%0,%1,%2,%3},{%4,%5,%6,%7},{%8,%9},{%0,%1,%2,%3};" \
                 : "+f"(d[0]), "+f"(d[1]), "+f"(d[2]), "+f"(d[3]) \
                 : "r"(a[0]), "r"(a[1]), "r"(a[2]), "r"(a[3]), "r"(b[0]), "r"(b[1]))

__global__ void __launch_bounds__(256, 2)
k_gemm_tc(const float* __restrict__ A, const float* __restrict__ Whi,
          const float* __restrict__ Wlo) {
    extern __shared__ float sm[];
    float* sAh = sm;
    float* sAl = sm + SA_ELEMS;
    float* sWh = sm + 2 * SA_ELEMS;
    float* sWl = sm + 2 * SA_ELEMS + SW_ELEMS;
    const unsigned* sAh_u = (const unsigned*)sAh;
    const unsigned* sAl_u = (const unsigned*)sAl;
    const unsigned* sWh_u = (const unsigned*)sWh;
    const unsigned* sWl_u = (const unsigned*)sWl;

    const int tid = threadIdx.x;
    const int lane = tid & 31, warp = tid >> 5;
    const int wm = warp >> 2, wn = warp & 3;   // wm 0..1 (64 rows), wn 0..3 (32 cols)
    const int g = lane >> 2, t4 = lane & 3;
    const int row0 = blockIdx.x * 128;

    float acc[4][4][4];
#pragma unroll
    for (int mt = 0; mt < 4; mt++)
#pragma unroll
        for (int nt = 0; nt < 4; nt++)
#pragma unroll
            for (int c = 0; c < 4; c++) acc[mt][nt][c] = 0.0f;

    const float4* Whv = (const float4*)Whi;
    const float4* Wlv = (const float4*)Wlo;

#pragma unroll
    for (int q = 0; q < 4; q++) {
        const int k0 = q * 32;
        __syncthreads();
        // stage A rows [row0,row0+128) x cols [k0,k0+32): 1024 float4, split
#pragma unroll
        for (int j = 0; j < 4; j++) {
            int idx = tid + 256 * j;
            int r = idx >> 3, c = idx & 7;
            int grow = row0 + r;
            float4 v = make_float4(0.f, 0.f, 0.f, 0.f);
            if (grow < NN) v = *(const float4*)&A[(size_t)grow * HH + k0 + c * 4];
            float4 hv, lv;
            tf32_split(v.x, hv.x, lv.x);
            tf32_split(v.y, hv.y, lv.y);
            tf32_split(v.z, hv.z, lv.z);
            tf32_split(v.w, hv.w, lv.w);
            *(float4*)&sAh[r * SA_STRIDE + c * 4] = hv;
            *(float4*)&sAl[r * SA_STRIDE + c * 4] = lv;
        }
        // stage W rows [k0,k0+32) x 128 cols: pure copy of pre-split halves
#pragma unroll
        for (int j = 0; j < 4; j++) {
            int idx = tid + 256 * j;
            int kr = idx >> 5, c = idx & 31;
            *(float4*)&sWh[kr * SW_STRIDE + c * 4] = Whv[(size_t)(k0 + kr) * 32 + c];
            *(float4*)&sWl[kr * SW_STRIDE + c * 4] = Wlv[(size_t)(k0 + kr) * 32 + c];
        }
        __syncthreads();

#pragma unroll
        for (int ks = 0; ks < 4; ks++) {
            unsigned ah[4][4], al[4][4];
#pragma unroll
            for (int mt = 0; mt < 4; mt++) {
                int rb = (wm * 64 + mt * 16 + g) * SA_STRIDE;
                int col = ks * 8 + t4;
                ah[mt][0] = sAh_u[rb + col];
                ah[mt][1] = sAh_u[rb + 8 * SA_STRIDE + col];
                ah[mt][2] = sAh_u[rb + col + 4];
                ah[mt][3] = sAh_u[rb + 8 * SA_STRIDE + col + 4];
                al[mt][0] = sAl_u[rb + col];
                al[mt][1] = sAl_u[rb + 8 * SA_STRIDE + col];
                al[mt][2] = sAl_u[rb + col + 4];
                al[mt][3] = sAl_u[rb + 8 * SA_STRIDE + col + 4];
            }
            unsigned bh[4][2], bl[4][2];
#pragma unroll
            for (int nt = 0; nt < 4; nt++) {
                int n = wn * 32 + nt * 8 + g;
                int kr = (ks * 8 + t4) * SW_STRIDE;
                bh[nt][0] = sWh_u[kr + n];
                bh[nt][1] = sWh_u[kr + 4 * SW_STRIDE + n];
                bl[nt][0] = sWl_u[kr + n];
                bl[nt][1] = sWl_u[kr + 4 * SW_STRIDE + n];
            }
#pragma unroll
            for (int mt = 0; mt < 4; mt++)
#pragma unroll
                for (int nt = 0; nt < 4; nt++) {
                    MMA8(acc[mt][nt], al[mt], bh[nt]);
                    MMA8(acc[mt][nt], ah[mt], bl[nt]);
                    MMA8(acc[mt][nt], ah[mt], bh[nt]);
                }
        }
    }

#pragma unroll
    for (int mt = 0; mt < 4; mt++) {
#pragma unroll
        for (int nt = 0; nt < 4; nt++) {
            int row = row0 + wm * 64 + mt * 16 + g;
            int col = wn * 32 + nt * 8 + t4 * 2;
            if (row < NN)
                *(float2*)&g_hw[(size_t)row * HH + col] =
                    make_float2(acc[mt][nt][0], acc[mt][nt][1]);
            if (row + 8 < NN)
                *(float2*)&g_hw[(size_t)(row + 8) * HH + col] =
                    make_float2(acc[mt][nt][2], acc[mt][nt][3]);
        }
    }
}

// ---------------- fused aggregate + bias + LayerNorm + GELU (+head) ----------
// EXACT round-2 version (best known): one warp per node, x2 unroll, cached loads.
__global__ void k_agg(const float* __restrict__ cb, const float* __restrict__ lg,
                      const float* __restrict__ lb, float* __restrict__ hout,
                      int do_gelu, const float* __restrict__ head_w,
                      const float* __restrict__ head_b, float* __restrict__ scores) {
    int gwarp = (blockIdx.x * blockDim.x + threadIdx.x) >> 5;
    int lane = threadIdx.x & 31;
    if (gwarp >= NN) return;
    int v = gwarp;
    int c4 = lane * 4;

    int beg = g_rowstart[v];
    int end = g_rowstart[v + 1];

    float a0 = 0.f, a1 = 0.f, a2 = 0.f, a3 = 0.f;
    int e = beg;
    for (; e + 2 <= end; e += 2) {
        int s0 = g_srcs[e], s1 = g_srcs[e + 1];
        float n0 = g_norms[e], n1 = g_norms[e + 1];
        float4 r0 = *(const float4*)&g_hw[(size_t)s0 * HH + c4];
        float4 r1 = *(const float4*)&g_hw[(size_t)s1 * HH + c4];
        a0 += r0.x * n0 + r1.x * n1;
        a1 += r0.y * n0 + r1.y * n1;
        a2 += r0.z * n0 + r1.z * n1;
        a3 += r0.w * n0 + r1.w * n1;
    }
    if (e < end) {
        int s0 = g_srcs[e];
        float n0 = g_norms[e];
        float4 r0 = *(const float4*)&g_hw[(size_t)s0 * HH + c4];
        a0 += r0.x * n0; a1 += r0.y * n0; a2 += r0.z * n0; a3 += r0.w * n0;
    }
    // self loop (fp32)
    float invd = g_invd[v];
    float4 sv = *(const float4*)&g_hw[(size_t)v * HH + c4];
    a0 += sv.x * invd; a1 += sv.y * invd; a2 += sv.z * invd; a3 += sv.w * invd;
    float4 bb = *(const float4*)&cb[c4];
    a0 += bb.x; a1 += bb.y; a2 += bb.z; a3 += bb.w;

    float sum = a0 + a1 + a2 + a3;
    float sq  = a0 * a0 + a1 * a1 + a2 * a2 + a3 * a3;
#pragma unroll
    for (int off = 16; off > 0; off >>= 1) {
        sum += __shfl_xor_sync(0xffffffffu, sum, off);
        sq  += __shfl_xor_sync(0xffffffffu, sq, off);
    }
    float mu = sum * (1.0f / 128.0f);
    float var = sq * (1.0f / 128.0f) - mu * mu;
    float rstd = rsqrtf(var + 1e-5f);

    float4 gg = *(const float4*)&lg[c4];
    float4 bl = *(const float4*)&lb[c4];
    a0 = (a0 - mu) * rstd * gg.x + bl.x;
    a1 = (a1 - mu) * rstd * gg.y + bl.y;
    a2 = (a2 - mu) * rstd * gg.z + bl.z;
    a3 = (a3 - mu) * rstd * gg.w + bl.w;

    if (do_gelu) {
        const float inv_sqrt2 = 0.7071067811865475f;
        a0 = 0.5f * a0 * (1.0f + erff(a0 * inv_sqrt2));
        a1 = 0.5f * a1 * (1.0f + erff(a1 * inv_sqrt2));
        a2 = 0.5f * a2 * (1.0f + erff(a2 * inv_sqrt2));
        a3 = 0.5f * a3 * (1.0f + erff(a3 * inv_sqrt2));
    }

    *(float4*)&hout[(size_t)v * HH + c4] = make_float4(a0, a1, a2, a3);

    if (scores) {
        float4 w = *(const float4*)&head_w[c4];
        float sc = a0 * w.x + a1 * w.y + a2 * w.z + a3 * w.w;
#pragma unroll
        for (int off = 16; off > 0; off >>= 1)
            sc += __shfl_xor_sync(0xffffffffu, sc, off);
        if (lane == 0) scores[v] = sc + head_b[0];
    }
}

// ---------------- launch ------------------------------------------------------
extern "C" void kernel_launch(void* const* d_in, const int* in_sizes, int n_in,
                              void* d_out, int out_size) {
    const float* x      = (const float*)d_in[0];
    const int*   ei     = (const int*)  d_in[1];
    const float* conv_w = (const float*)d_in[2];
    const float* conv_b = (const float*)d_in[3];
    const float* ln_g   = (const float*)d_in[4];
    const float* ln_b   = (const float*)d_in[5];
    const float* head_w = (const float*)d_in[6];
    const float* head_b = (const float*)d_in[7];
    float* out = (float*)d_out;            // [0,N) scores, [N, N+N*128) h

    const int* src = ei;
    const int* dst = ei + EE;

    static const int GEMM_SMEM = GEMM_SMEM_FLOATS * (int)sizeof(float); // ~71.7KB
    cudaFuncSetAttribute(k_gemm_tc, cudaFuncAttributeMaxDynamicSharedMemorySize, GEMM_SMEM);

    void* h_dev = nullptr;
    cudaGetSymbolAddress(&h_dev, g_h);

    void* whi_dev = nullptr; void* wlo_dev = nullptr;
    cudaGetSymbolAddress(&whi_dev, g_whi);
    cudaGetSymbolAddress(&wlo_dev, g_wlo);

    k_init     <<<(NN + 255) / 256, 256>>> ();
    k_splitw   <<<(LL * HH * HH) / 256, 256>>> (conv_w);
    k_count    <<<(EE + 255) / 256, 256>>> (dst);
    k_blocksum <<<SB, 256>>> ();
    k_scanpart <<<1, 256>>> ();
    k_blockscan<<<SB, 256>>> ();
    k_fill     <<<(EE + 255) / 256, 256>>> (src, dst);

    for (int l = 0; l < LL; l++) {
        const float* A = (l == 0) ? x : (const float*)h_dev;
        k_gemm_tc<<<(NN + 127) / 128, 256, GEMM_SMEM>>>(
            A, (const float*)whi_dev + (size_t)l * HH * HH,
               (const float*)wlo_dev + (size_t)l * HH * HH);

        bool last = (l == LL - 1);
        float* hout = last ? (out + NN) : (float*)h_dev;
        k_agg<<<(NN * 32 + 255) / 256, 256>>>(
            conv_b + (size_t)l * HH, ln_g + (size_t)l * HH, ln_b + (size_t)l * HH,
            hout, last ? 0 : 1, head_w, head_b, last ? out : nullptr);
    }
}

// round 7
// speedup vs baseline: 1.0279x; 1.0279x over previous
#include <cuda_runtime.h>
#include <math.h>
#include <stdint.h>

#define NN 50000
#define EE 800000
#define HH 128
#define LL 4
#define SB 196   // scan blocks = ceil(NN/256)

// ---------------- scratch (static device globals; no allocation) -------------
__device__ float g_hw[(size_t)NN * HH];       // h @ W result per layer
__device__ float g_h[(size_t)NN * HH];        // activations between layers
__device__ int   g_cnt[NN];
__device__ int   g_cursor[NN];
__device__ int   g_rowstart[NN + 1];
__device__ float g_isd[NN];                   // 1/sqrt(deg)
__device__ float g_invd[NN];                  // 1/deg
__device__ int   g_srcs[EE];                  // CSR: src node per (dst-sorted) edge
__device__ float g_norms[EE];                 // CSR: isd[src]*isd[dst]
__device__ int   g_part[256];                 // scan partials

// ---------------- setup kernels ----------------------------------------------
__global__ void k_init() {
    int i = blockIdx.x * blockDim.x + threadIdx.x;
    if (i < NN) { g_cnt[i] = 0; g_cursor[i] = 0; }
}

__global__ void k_count(const int* __restrict__ dst) {
    int e = blockIdx.x * blockDim.x + threadIdx.x;
    if (e < EE) atomicAdd(&g_cnt[dst[e]], 1);
}

__global__ void k_blocksum() {
    int i = blockIdx.x * 256 + threadIdx.x;
    int v = (i < NN) ? g_cnt[i] : 0;
    int lane = threadIdx.x & 31, w = threadIdx.x >> 5;
    __shared__ int ws[8];
#pragma unroll
    for (int o = 16; o > 0; o >>= 1) v += __shfl_down_sync(0xffffffffu, v, o);
    if (lane == 0) ws[w] = v;
    __syncthreads();
    if (threadIdx.x == 0) {
        int s = 0;
#pragma unroll
        for (int j = 0; j < 8; j++) s += ws[j];
        g_part[blockIdx.x] = s;
    }
}

__global__ void k_scanpart() {
    int t = threadIdx.x;
    int v = (t < SB) ? g_part[t] : 0;
    int lane = t & 31, w = t >> 5;
    int x = v;
#pragma unroll
    for (int o = 1; o < 32; o <<= 1) {
        int y = __shfl_up_sync(0xffffffffu, x, o);
        if (lane >= o) x += y;
    }
    __shared__ int ws[8];
    if (lane == 31) ws[w] = x;
    __syncthreads();
    if (t == 0) {
        int run = 0;
#pragma unroll
        for (int j = 0; j < 8; j++) { int tmp = ws[j]; ws[j] = run; run += tmp; }
    }
    __syncthreads();
    int incl = x + ws[w];
    if (t < SB) g_part[t] = incl - v;
}

__global__ void k_blockscan() {
    int b = blockIdx.x;
    int i = b * 256 + threadIdx.x;
    int v = (i < NN) ? g_cnt[i] : 0;
    int lane = threadIdx.x & 31, w = threadIdx.x >> 5;
    int x = v;
#pragma unroll
    for (int o = 1; o < 32; o <<= 1) {
        int y = __shfl_up_sync(0xffffffffu, x, o);
        if (lane >= o) x += y;
    }
    __shared__ int ws[8];
    if (lane == 31) ws[w] = x;
    __syncthreads();
    if (threadIdx.x == 0) {
        int run = 0;
#pragma unroll
        for (int j = 0; j < 8; j++) { int tmp = ws[j]; ws[j] = run; run += tmp; }
    }
    __syncthreads();
    int incl = x + ws[w];
    int ex = incl - v;
    int base = g_part[b];
    if (i < NN) {
        g_rowstart[i] = base + ex;
        float deg = (float)v + 1.0f;
        g_isd[i]  = rsqrtf(deg);
        g_invd[i] = 1.0f / deg;
    }
    if (i == NN - 1) g_rowstart[NN] = base + ex + v;
}

__global__ void k_fill(const int* __restrict__ src, const int* __restrict__ dst) {
    int e = blockIdx.x * blockDim.x + threadIdx.x;
    if (e < EE) {
        int s = src[e], d = dst[e];
        int pos = atomicAdd(&g_cursor[d], 1);
        int idx = g_rowstart[d] + pos;
        g_srcs[idx]  = s;
        g_norms[idx] = g_isd[s] * g_isd[d];
    }
}

// ---------------- 3xTF32 tensor-core GEMM (exact round-2 version) ------------
#define SA_STRIDE 68
#define SW_STRIDE 136
#define SA_ELEMS (128 * SA_STRIDE)
#define SW_ELEMS (64 * SW_STRIDE)
#define GEMM_SMEM_FLOATS (2 * SA_ELEMS + 2 * SW_ELEMS)

__device__ __forceinline__ void tf32_split(float x, float& hi, float& lo) {
    unsigned h, l;
    asm("cvt.rna.tf32.f32 %0, %1;" : "=r"(h) : "f"(x));
    float r = x - __uint_as_float(h);
    asm("cvt.rna.tf32.f32 %0, %1;" : "=r"(l) : "f"(r));
    hi = __uint_as_float(h);
    lo = __uint_as_float(l);
}

#define MMA8(d, a, b) \
    asm volatile("mma.sync.aligned.m16n8k8.row.col.f32.tf32.tf32.f32 " \
                 "{%0,%1,%2,%3},{%4,%5,%6,%7},{%8,%9},{%0,%1,%2,%3};" \
                 : "+f"(d[0]), "+f"(d[1]), "+f"(d[2]), "+f"(d[3]) \
                 : "r"(a[0]), "r"(a[1]), "r"(a[2]), "r"(a[3]), "r"(b[0]), "r"(b[1]))

__global__ void __launch_bounds__(256, 1)
k_gemm_tc(const float* __restrict__ A, const float* __restrict__ W) {
    extern __shared__ float sm[];
    float* sAh = sm;
    float* sAl = sm + SA_ELEMS;
    float* sWh = sm + 2 * SA_ELEMS;
    float* sWl = sm + 2 * SA_ELEMS + SW_ELEMS;
    const unsigned* sAh_u = (const unsigned*)sAh;
    const unsigned* sAl_u = (const unsigned*)sAl;
    const unsigned* sWh_u = (const unsigned*)sWh;
    const unsigned* sWl_u = (const unsigned*)sWl;

    const int tid = threadIdx.x;
    const int lane = tid & 31, warp = tid >> 5;
    const int wm = warp >> 2, wn = warp & 3;
    const int g = lane >> 2, t4 = lane & 3;
    const int row0 = blockIdx.x * 128;

    float acc[4][4][4];
#pragma unroll
    for (int mt = 0; mt < 4; mt++)
#pragma unroll
        for (int nt = 0; nt < 4; nt++)
#pragma unroll
            for (int c = 0; c < 4; c++) acc[mt][nt][c] = 0.0f;

    const float4* Wv = (const float4*)W;

    for (int half = 0; half < 2; half++) {
        const int k0 = half * 64;
        __syncthreads();
#pragma unroll
        for (int j = 0; j < 8; j++) {
            int idx = tid + 256 * j;
            int r = idx >> 4, c = idx & 15;
            int grow = row0 + r;
            float4 v = make_float4(0.f, 0.f, 0.f, 0.f);
            if (grow < NN) v = *(const float4*)&A[(size_t)grow * HH + k0 + c * 4];
            float4 hv, lv;
            tf32_split(v.x, hv.x, lv.x);
            tf32_split(v.y, hv.y, lv.y);
            tf32_split(v.z, hv.z, lv.z);
            tf32_split(v.w, hv.w, lv.w);
            *(float4*)&sAh[r * SA_STRIDE + c * 4] = hv;
            *(float4*)&sAl[r * SA_STRIDE + c * 4] = lv;
        }
#pragma unroll
        for (int j = 0; j < 8; j++) {
            int idx = tid + 256 * j;
            int kr = idx >> 5, c = idx & 31;
            float4 v = Wv[(size_t)(k0 + kr) * 32 + c];
            float4 hv, lv;
            tf32_split(v.x, hv.x, lv.x);
            tf32_split(v.y, hv.y, lv.y);
            tf32_split(v.z, hv.z, lv.z);
            tf32_split(v.w, hv.w, lv.w);
            *(float4*)&sWh[kr * SW_STRIDE + c * 4] = hv;
            *(float4*)&sWl[kr * SW_STRIDE + c * 4] = lv;
        }
        __syncthreads();

        for (int ks = 0; ks < 8; ks++) {
            unsigned ah[4][4], al[4][4];
#pragma unroll
            for (int mt = 0; mt < 4; mt++) {
                int rb = (wm * 64 + mt * 16 + g) * SA_STRIDE;
                int col = ks * 8 + t4;
                ah[mt][0] = sAh_u[rb + col];
                ah[mt][1] = sAh_u[rb + 8 * SA_STRIDE + col];
                ah[mt][2] = sAh_u[rb + col + 4];
                ah[mt][3] = sAh_u[rb + 8 * SA_STRIDE + col + 4];
                al[mt][0] = sAl_u[rb + col];
                al[mt][1] = sAl_u[rb + 8 * SA_STRIDE + col];
                al[mt][2] = sAl_u[rb + col + 4];
                al[mt][3] = sAl_u[rb + 8 * SA_STRIDE + col + 4];
            }
            unsigned bh[4][2], bl[4][2];
#pragma unroll
            for (int nt = 0; nt < 4; nt++) {
                int n = wn * 32 + nt * 8 + g;
                int kr = (ks * 8 + t4) * SW_STRIDE;
                bh[nt][0] = sWh_u[kr + n];
                bh[nt][1] = sWh_u[kr + 4 * SW_STRIDE + n];
                bl[nt][0] = sWl_u[kr + n];
                bl[nt][1] = sWl_u[kr + 4 * SW_STRIDE + n];
            }
#pragma unroll
            for (int mt = 0; mt < 4; mt++)
#pragma unroll
                for (int nt = 0; nt < 4; nt++) {
                    MMA8(acc[mt][nt], al[mt], bh[nt]);
                    MMA8(acc[mt][nt], ah[mt], bl[nt]);
                    MMA8(acc[mt][nt], ah[mt], bh[nt]);
                }
        }
    }

#pragma unroll
    for (int mt = 0; mt < 4; mt++) {
#pragma unroll
        for (int nt = 0; nt < 4; nt++) {
            int row = row0 + wm * 64 + mt * 16 + g;
            int col = wn * 32 + nt * 8 + t4 * 2;
            if (row < NN)
                *(float2*)&g_hw[(size_t)row * HH + col] =
                    make_float2(acc[mt][nt][0], acc[mt][nt][1]);
            if (row + 8 < NN)
                *(float2*)&g_hw[(size_t)(row + 8) * HH + col] =
                    make_float2(acc[mt][nt][2], acc[mt][nt][3]);
        }
    }
}

// ---------------- fused aggregate + bias + LayerNorm + GELU (+head) ----------
// EXACT round-2 version: one warp per node, x2 unroll, cached loads.
__global__ void k_agg(const float* __restrict__ cb, const float* __restrict__ lg,
                      const float* __restrict__ lb, float* __restrict__ hout,
                      int do_gelu, const float* __restrict__ head_w,
                      const float* __restrict__ head_b, float* __restrict__ scores) {
    int gwarp = (blockIdx.x * blockDim.x + threadIdx.x) >> 5;
    int lane = threadIdx.x & 31;
    if (gwarp >= NN) return;
    int v = gwarp;
    int c4 = lane * 4;

    int beg = g_rowstart[v];
    int end = g_rowstart[v + 1];

    float a0 = 0.f, a1 = 0.f, a2 = 0.f, a3 = 0.f;
    int e = beg;
    for (; e + 2 <= end; e += 2) {
        int s0 = g_srcs[e], s1 = g_srcs[e + 1];
        float n0 = g_norms[e], n1 = g_norms[e + 1];
        float4 r0 = *(const float4*)&g_hw[(size_t)s0 * HH + c4];
        float4 r1 = *(const float4*)&g_hw[(size_t)s1 * HH + c4];
        a0 += r0.x * n0 + r1.x * n1;
        a1 += r0.y * n0 + r1.y * n1;
        a2 += r0.z * n0 + r1.z * n1;
        a3 += r0.w * n0 + r1.w * n1;
    }
    if (e < end) {
        int s0 = g_srcs[e];
        float n0 = g_norms[e];
        float4 r0 = *(const float4*)&g_hw[(size_t)s0 * HH + c4];
        a0 += r0.x * n0; a1 += r0.y * n0; a2 += r0.z * n0; a3 += r0.w * n0;
    }
    float invd = g_invd[v];
    float4 sv = *(const float4*)&g_hw[(size_t)v * HH + c4];
    a0 += sv.x * invd; a1 += sv.y * invd; a2 += sv.z * invd; a3 += sv.w * invd;
    float4 bb = *(const float4*)&cb[c4];
    a0 += bb.x; a1 += bb.y; a2 += bb.z; a3 += bb.w;

    float sum = a0 + a1 + a2 + a3;
    float sq  = a0 * a0 + a1 * a1 + a2 * a2 + a3 * a3;
#pragma unroll
    for (int off = 16; off > 0; off >>= 1) {
        sum += __shfl_xor_sync(0xffffffffu, sum, off);
        sq  += __shfl_xor_sync(0xffffffffu, sq, off);
    }
    float mu = sum * (1.0f / 128.0f);
    float var = sq * (1.0f / 128.0f) - mu * mu;
    float rstd = rsqrtf(var + 1e-5f);

    float4 gg = *(const float4*)&lg[c4];
    float4 bl = *(const float4*)&lb[c4];
    a0 = (a0 - mu) * rstd * gg.x + bl.x;
    a1 = (a1 - mu) * rstd * gg.y + bl.y;
    a2 = (a2 - mu) * rstd * gg.z + bl.z;
    a3 = (a3 - mu) * rstd * gg.w + bl.w;

    if (do_gelu) {
        const float inv_sqrt2 = 0.7071067811865475f;
        a0 = 0.5f * a0 * (1.0f + erff(a0 * inv_sqrt2));
        a1 = 0.5f * a1 * (1.0f + erff(a1 * inv_sqrt2));
        a2 = 0.5f * a2 * (1.0f + erff(a2 * inv_sqrt2));
        a3 = 0.5f * a3 * (1.0f + erff(a3 * inv_sqrt2));
    }

    *(float4*)&hout[(size_t)v * HH + c4] = make_float4(a0, a1, a2, a3);

    if (scores) {
        float4 w = *(const float4*)&head_w[c4];
        float sc = a0 * w.x + a1 * w.y + a2 * w.z + a3 * w.w;
#pragma unroll
        for (int off = 16; off > 0; off >>= 1)
            sc += __shfl_xor_sync(0xffffffffu, sc, off);
        if (lane == 0) scores[v] = sc + head_b[0];
    }
}

// ---------------- launch ------------------------------------------------------
extern "C" void kernel_launch(void* const* d_in, const int* in_sizes, int n_in,
                              void* d_out, int out_size) {
    const float* x      = (const float*)d_in[0];
    const int*   ei     = (const int*)  d_in[1];
    const float* conv_w = (const float*)d_in[2];
    const float* conv_b = (const float*)d_in[3];
    const float* ln_g   = (const float*)d_in[4];
    const float* ln_b   = (const float*)d_in[5];
    const float* head_w = (const float*)d_in[6];
    const float* head_b = (const float*)d_in[7];
    float* out = (float*)d_out;            // [0,N) scores, [N, N+N*128) h

    const int* src = ei;
    const int* dst = ei + EE;

    static const int GEMM_SMEM = GEMM_SMEM_FLOATS * (int)sizeof(float); // ~136KB
    cudaFuncSetAttribute(k_gemm_tc, cudaFuncAttributeMaxDynamicSharedMemorySize, GEMM_SMEM);

    void* h_dev = nullptr;
    cudaGetSymbolAddress(&h_dev, g_h);

    // side stream + events for capture fork-join (host resources, created once)
    static cudaStream_t s2 = nullptr;
    static cudaEvent_t  evFork = nullptr, evJoin = nullptr;
    if (!s2) {
        cudaStreamCreateWithFlags(&s2, cudaStreamNonBlocking);
        cudaEventCreateWithFlags(&evFork, cudaEventDisableTiming);
        cudaEventCreateWithFlags(&evJoin, cudaEventDisableTiming);
    }

    // fork: layer-0 GEMM runs concurrently with CSR build
    cudaEventRecord(evFork, 0);
    cudaStreamWaitEvent(s2, evFork, 0);
    k_gemm_tc<<<(NN + 127) / 128, 256, GEMM_SMEM, s2>>>(x, conv_w);
    cudaEventRecord(evJoin, s2);

    // CSR build on main stream (independent of gemm l0)
    k_init     <<<(NN + 255) / 256, 256>>> ();
    k_count    <<<(EE + 255) / 256, 256>>> (dst);
    k_blocksum <<<SB, 256>>> ();
    k_scanpart <<<1, 256>>> ();
    k_blockscan<<<SB, 256>>> ();
    k_fill     <<<(EE + 255) / 256, 256>>> (src, dst);

    // join before first aggregation
    cudaStreamWaitEvent(0, evJoin, 0);

    for (int l = 0; l < LL; l++) {
        if (l > 0)
            k_gemm_tc<<<(NN + 127) / 128, 256, GEMM_SMEM>>>(
                (const float*)h_dev, conv_w + (size_t)l * HH * HH);

        bool last = (l == LL - 1);
        float* hout = last ? (out + NN) : (float*)h_dev;
        k_agg<<<(NN * 32 + 255) / 256, 256>>>(
            conv_b + (size_t)l * HH, ln_g + (size_t)l * HH, ln_b + (size_t)l * HH,
            hout, last ? 0 : 1, head_w, head_b, last ? out : nullptr);
    }
}